// round 1
// baseline (speedup 1.0000x reference)
#include <cuda_runtime.h>
#include <math.h>

#define KHW     3
#define HIN     14
#define WIN     14
#define HO      12
#define WO      12
#define BATCH   4
#define FIN     32
#define DIN     8
#define FF      32          // filters out
#define CCAP    288         // caps per patch = 9*32
#define DOUT    16
#define NPOS    (BATCH*HO*WO)   // 576
#define NCH     6               // c-chunks
#define CPC     (CCAP/NCH)      // 48
#define WARPS   12
#define TPB     (WARPS*32)      // 384
#define POSB    (WARPS*2)       // 24 positions per CTA
#define NPB     (NPOS/POSB)     // 24 position blocks

// ---------------- scratch (static device globals; no allocation) -------------
__device__ float g_Wt[(size_t)CCAP*32*32*4];          // [c][jv(32)][f(32)][4]  (float4 units)
__device__ float g_S1p[(size_t)NCH*NPOS*FF*DOUT];     // partial sum-over-c of preds
__device__ float g_out1[(size_t)NPOS*FF*DOUT];        // squash(centroid iter1)
__device__ float g_centp[(size_t)NCH*NPOS*FF*DOUT];   // partial centroids iter2

// ---------------- W transpose: W[f][c][o][i] -> Wt[c][j][f] ------------------
__global__ void k_transpose(const float* __restrict__ W) {
    int tid = blockIdx.x * blockDim.x + threadIdx.x;
    if (tid >= CCAP * FF * 32) return;
    int jv = tid & 31;                // float4 index within the 128-float (o,i) row
    int f  = (tid >> 5) & 31;
    int c  = tid >> 10;
    float4 v = ((const float4*)W)[((size_t)f * CCAP + c) * 32 + jv];
    ((float4*)g_Wt)[((size_t)c * 32 + jv) * 32 + f] = v;
}

// decode position -> base pointer into x
__device__ __forceinline__ const float* pos_base(const float* x, int pos) {
    int b = pos / (HO * WO);
    int r = pos % (HO * WO);
    int h = r / WO;
    int w = r % WO;
    return x + (((size_t)(b * HIN + h) * WIN) + w) * (FIN * DIN);
}

// per-(c) pred computation for 2 positions; lane = f; pr[o] accumulated
__device__ __forceinline__ void pred_c(int c, const float* xb0, const float* xb1,
                                       int lane, float pr0[DOUT], float pr1[DOUT]) {
    int kk  = c >> 5;          // kh*3+kw
    int fin = c & 31;
    int kh  = kk / 3;
    int kw  = kk - kh * 3;
    int off = ((kh * WIN + kw) * FIN + fin) * DIN;   // floats
    const float4* xp0 = (const float4*)(xb0 + off);
    const float4* xp1 = (const float4*)(xb1 + off);
    float4 p00 = xp0[0], p01 = xp0[1];
    float4 p10 = xp1[0], p11 = xp1[1];
    const float4* wp = ((const float4*)g_Wt) + (size_t)c * 1024 + lane;
    #pragma unroll
    for (int jv = 0; jv < 32; ++jv) {
        float4 wv = wp[(size_t)jv * 32];
        const float4 pa = (jv & 1) ? p01 : p00;
        const float4 pb = (jv & 1) ? p11 : p10;
        int o = jv >> 1;
        pr0[o] += wv.x * pa.x + wv.y * pa.y + wv.z * pa.z + wv.w * pa.w;
        pr1[o] += wv.x * pb.x + wv.y * pb.y + wv.z * pb.z + wv.w * pb.w;
    }
}

// ---------------- pass 1: S1[pos,f,o] partial = sum_{c in chunk} preds -------
__global__ void __launch_bounds__(TPB, 1) k_pass1(const float* __restrict__ x) {
    int lane = threadIdx.x & 31;
    int w    = threadIdx.x >> 5;
    int pos0 = blockIdx.x * POSB + w * 2;
    int pos1 = pos0 + 1;
    int cch  = blockIdx.y;
    const float* xb0 = pos_base(x, pos0);
    const float* xb1 = pos_base(x, pos1);

    float a0[DOUT], a1[DOUT];
    #pragma unroll
    for (int o = 0; o < DOUT; ++o) { a0[o] = 0.f; a1[o] = 0.f; }

    int cbeg = cch * CPC;
    for (int c = cbeg; c < cbeg + CPC; ++c)
        pred_c(c, xb0, xb1, lane, a0, a1);

    float4* d0 = (float4*)(g_S1p + (((size_t)cch * NPOS + pos0) * FF + lane) * DOUT);
    float4* d1 = (float4*)(g_S1p + (((size_t)cch * NPOS + pos1) * FF + lane) * DOUT);
    #pragma unroll
    for (int q = 0; q < 4; ++q) {
        d0[q] = make_float4(a0[q*4], a0[q*4+1], a0[q*4+2], a0[q*4+3]);
        d1[q] = make_float4(a1[q*4], a1[q*4+1], a1[q*4+2], a1[q*4+3]);
    }
}

// ---------------- squash 1: out1 = squash(sum(partials)/32) ------------------
__global__ void k_squash1() {
    int t = blockIdx.x * blockDim.x + threadIdx.x;   // (pos,f)
    if (t >= NPOS * FF) return;
    float s[DOUT];
    #pragma unroll
    for (int o = 0; o < DOUT; ++o) s[o] = 0.f;
    for (int ch = 0; ch < NCH; ++ch) {
        const float* p = g_S1p + ((size_t)ch * NPOS * FF + t) * DOUT;
        #pragma unroll
        for (int o = 0; o < DOUT; ++o) s[o] += p[o];
    }
    float sn = 0.f;
    #pragma unroll
    for (int o = 0; o < DOUT; ++o) { s[o] *= (1.f / 32.f); sn += s[o] * s[o]; }
    float sc = (sn / (1.f + sn)) / sqrtf(sn + 1e-7f);
    float* d = g_out1 + (size_t)t * DOUT;
    #pragma unroll
    for (int o = 0; o < DOUT; ++o) d[o] = s[o] * sc;
}

// ---------------- pass 2: fused agreement/softmax(F)/centroid ----------------
__global__ void __launch_bounds__(TPB, 1) k_pass2(const float* __restrict__ x) {
    int lane = threadIdx.x & 31;
    int w    = threadIdx.x >> 5;
    int pos0 = blockIdx.x * POSB + w * 2;
    int pos1 = pos0 + 1;
    int cch  = blockIdx.y;
    const float* xb0 = pos_base(x, pos0);
    const float* xb1 = pos_base(x, pos1);

    // out1 for (pos, f=lane)
    float o10[DOUT], o11[DOUT];
    {
        const float* q0 = g_out1 + (((size_t)pos0 * FF) + lane) * DOUT;
        const float* q1 = g_out1 + (((size_t)pos1 * FF) + lane) * DOUT;
        #pragma unroll
        for (int o = 0; o < DOUT; ++o) { o10[o] = q0[o]; o11[o] = q1[o]; }
    }

    float ce0[DOUT], ce1[DOUT];
    #pragma unroll
    for (int o = 0; o < DOUT; ++o) { ce0[o] = 0.f; ce1[o] = 0.f; }

    int cbeg = cch * CPC;
    for (int c = cbeg; c < cbeg + CPC; ++c) {
        float pr0[DOUT], pr1[DOUT];
        #pragma unroll
        for (int o = 0; o < DOUT; ++o) { pr0[o] = 0.f; pr1[o] = 0.f; }
        pred_c(c, xb0, xb1, lane, pr0, pr1);

        float ag0 = 0.f, ag1 = 0.f;
        #pragma unroll
        for (int o = 0; o < DOUT; ++o) { ag0 += pr0[o] * o10[o]; ag1 += pr1[o] * o11[o]; }

        // softmax over f == over the 32 lanes
        float m0 = ag0, m1 = ag1;
        #pragma unroll
        for (int d = 16; d > 0; d >>= 1) {
            m0 = fmaxf(m0, __shfl_xor_sync(0xffffffffu, m0, d));
            m1 = fmaxf(m1, __shfl_xor_sync(0xffffffffu, m1, d));
        }
        float e0 = __expf(ag0 - m0), e1 = __expf(ag1 - m1);
        float s0 = e0, s1 = e1;
        #pragma unroll
        for (int d = 16; d > 0; d >>= 1) {
            s0 += __shfl_xor_sync(0xffffffffu, s0, d);
            s1 += __shfl_xor_sync(0xffffffffu, s1, d);
        }
        float cc0 = e0 / s0, cc1 = e1 / s1;

        #pragma unroll
        for (int o = 0; o < DOUT; ++o) { ce0[o] += cc0 * pr0[o]; ce1[o] += cc1 * pr1[o]; }
    }

    float4* d0 = (float4*)(g_centp + (((size_t)cch * NPOS + pos0) * FF + lane) * DOUT);
    float4* d1 = (float4*)(g_centp + (((size_t)cch * NPOS + pos1) * FF + lane) * DOUT);
    #pragma unroll
    for (int q = 0; q < 4; ++q) {
        d0[q] = make_float4(ce0[q*4], ce0[q*4+1], ce0[q*4+2], ce0[q*4+3]);
        d1[q] = make_float4(ce1[q*4], ce1[q*4+1], ce1[q*4+2], ce1[q*4+3]);
    }
}

// ---------------- squash 2: final output ------------------------------------
__global__ void k_squash2(float* __restrict__ out) {
    int t = blockIdx.x * blockDim.x + threadIdx.x;   // (pos,f)
    if (t >= NPOS * FF) return;
    float s[DOUT];
    #pragma unroll
    for (int o = 0; o < DOUT; ++o) s[o] = 0.f;
    for (int ch = 0; ch < NCH; ++ch) {
        const float* p = g_centp + ((size_t)ch * NPOS * FF + t) * DOUT;
        #pragma unroll
        for (int o = 0; o < DOUT; ++o) s[o] += p[o];
    }
    float sn = 0.f;
    #pragma unroll
    for (int o = 0; o < DOUT; ++o) sn += s[o] * s[o];
    float sc = (sn / (1.f + sn)) / sqrtf(sn + 1e-7f);
    float* d = out + (size_t)t * DOUT;
    #pragma unroll
    for (int o = 0; o < DOUT; ++o) d[o] = s[o] * sc;
}

// -----------------------------------------------------------------------------
extern "C" void kernel_launch(void* const* d_in, const int* in_sizes, int n_in,
                              void* d_out, int out_size) {
    const float* x = (const float*)d_in[0];
    const float* W = (const float*)d_in[1];
    // robustness: identify by element count (x=200704, W=1179648)
    if (n_in >= 2 && in_sizes[0] == (int)((size_t)FF * CCAP * DOUT * DIN)) {
        const float* t = x; x = W; W = t;
    }
    float* out = (float*)d_out;

    k_transpose<<<(CCAP * FF * 32 + 255) / 256, 256>>>(W);
    k_pass1<<<dim3(NPB, NCH), TPB>>>(x);
    k_squash1<<<(NPOS * FF + 255) / 256, 256>>>();
    k_pass2<<<dim3(NPB, NCH), TPB>>>(x);
    k_squash2<<<(NPOS * FF + 255) / 256, 256>>>(out);
}